// round 12
// baseline (speedup 1.0000x reference)
#include <cuda_runtime.h>
#include <cuda_bf16.h>
#include <math.h>

#define B_ 4
#define V_ 50000
#define C_ 256
#define K_ 128
#define LAMBDA 100.0f
#define NCHUNK 19
#define TPC 165
#define NTILES 3125
#define LDI 129
#define CG_ITERS 48

__device__ float g_part1[(size_t)NCHUNK * 8 * K_ * C_];
__device__ float g_A[8 * K_ * C_];
__device__ float g_AA2[2 * 2 * B_ * K_ * K_];

__device__ __forceinline__ unsigned smem_u32(const void* p) {
    unsigned a;
    asm("{ .reg .u64 t; cvta.to.shared.u64 t, %1; cvt.u32.u64 %0, t; }" : "=r"(a) : "l"(p));
    return a;
}
__device__ __forceinline__ void cvt2(float x, float y, unsigned& hi, unsigned& lo) {
    __nv_bfloat162 h = __floats2bfloat162_rn(x, y);
    __nv_bfloat162 l = __floats2bfloat162_rn(x - __bfloat162float(h.x),
                                             y - __bfloat162float(h.y));
    hi = *(unsigned*)&h;
    lo = *(unsigned*)&l;
}
__device__ __forceinline__ void ldx4(unsigned* r, unsigned a) {
    asm volatile("ldmatrix.sync.aligned.m8n8.x4.shared.b16 {%0,%1,%2,%3}, [%4];"
                 : "=r"(r[0]), "=r"(r[1]), "=r"(r[2]), "=r"(r[3]) : "r"(a));
}
__device__ __forceinline__ void ldx2t(unsigned* r, unsigned a) {
    asm volatile("ldmatrix.sync.aligned.m8n8.x2.trans.shared.b16 {%0,%1}, [%2];"
                 : "=r"(r[0]), "=r"(r[1]) : "r"(a));
}
__device__ __forceinline__ void mma16816(float* d, const unsigned* a, const unsigned* b) {
    asm volatile("mma.sync.aligned.m16n8k16.row.col.f32.bf16.bf16.f32 "
                 "{%0,%1,%2,%3}, {%4,%5,%6,%7}, {%8,%9}, {%0,%1,%2,%3};"
                 : "+f"(d[0]), "+f"(d[1]), "+f"(d[2]), "+f"(d[3])
                 : "r"(a[0]), "r"(a[1]), "r"(a[2]), "r"(a[3]), "r"(b[0]), "r"(b[1]));
}

// ---------------------------------------------------------------------------
// GEMM1 via mma.sync bf16 hi/lo split (3 passes, single fp32 accumulator),
// software-pipelined: tile t+1's LDG issues before tile t's MMA.
// ---------------------------------------------------------------------------
__global__ __launch_bounds__(256, 2)
void gemm1_mma(const float* __restrict__ fx, const float* __restrict__ fy,
               const float* __restrict__ ex, const float* __restrict__ ey)
{
    __shared__ __align__(16) __nv_bfloat16 Ah[128 * 24], Al[128 * 24];   // stride 48B
    __shared__ __align__(16) __nv_bfloat16 Bh[16 * 136], Bl[16 * 136];   // stride 272B

    const int chunk = blockIdx.x, ntile = blockIdx.y, p = blockIdx.z;
    const int b = p >> 1, which = p & 1;
    const float* E = (which ? ey : ex) + (size_t)b * K_ * V_;
    const float* F = (which ? fy : fx) + (size_t)b * V_ * C_ + ntile * 128;
    float* out = g_part1 + ((size_t)chunk * 8 + which * 4 + b) * K_ * C_ + ntile * 128;

    const int tid = threadIdx.x, wid = tid >> 5, lane = tid & 31;
    const int wm = (wid >> 1) * 32, wn = (wid & 1) * 64;

    const int ar = tid >> 1, ahalf = tid & 1;
    const int fv = tid >> 4, fc = (tid & 15) * 8;

    const unsigned aAh = smem_u32(Ah), aAl = smem_u32(Al);
    const unsigned aBh = smem_u32(Bh), aBl = smem_u32(Bl);

    float acc[2][8][4];
#pragma unroll
    for (int mt = 0; mt < 2; ++mt)
#pragma unroll
        for (int nt = 0; nt < 8; ++nt)
#pragma unroll
            for (int e = 0; e < 4; ++e) acc[mt][nt][e] = 0.0f;

    const unsigned aoffH0 = aAh + (wm + (lane & 15)) * 48 + (lane >> 4) * 16;
    const unsigned aoffL0 = aAl + (wm + (lane & 15)) * 48 + (lane >> 4) * 16;
    const unsigned brow = (lane & 15);

    const int t0 = chunk * TPC;
    const int t1 = (t0 + TPC < NTILES) ? (t0 + TPC) : NTILES;

    const float* Ebase = E + (size_t)ar * V_ + ahalf * 8;

    float4 e0, e1, f0, f1;
    {
        const int vb = t0 << 4;
        e0 = *(const float4*)(Ebase + vb);
        e1 = *(const float4*)(Ebase + vb + 4);
        const float* Fp = F + (size_t)(vb + fv) * C_ + fc;
        f0 = *(const float4*)(Fp);
        f1 = *(const float4*)(Fp + 4);
    }

    for (int t = t0; t < t1; ++t) {
        __syncthreads();
        {
            unsigned h[4], l[4];
            cvt2(e0.x, e0.y, h[0], l[0]); cvt2(e0.z, e0.w, h[1], l[1]);
            cvt2(e1.x, e1.y, h[2], l[2]); cvt2(e1.z, e1.w, h[3], l[3]);
            *(uint4*)((char*)Ah + ar * 48 + ahalf * 16) = make_uint4(h[0], h[1], h[2], h[3]);
            *(uint4*)((char*)Al + ar * 48 + ahalf * 16) = make_uint4(l[0], l[1], l[2], l[3]);
            cvt2(f0.x, f0.y, h[0], l[0]); cvt2(f0.z, f0.w, h[1], l[1]);
            cvt2(f1.x, f1.y, h[2], l[2]); cvt2(f1.z, f1.w, h[3], l[3]);
            *(uint4*)((char*)Bh + fv * 272 + fc * 2) = make_uint4(h[0], h[1], h[2], h[3]);
            *(uint4*)((char*)Bl + fv * 272 + fc * 2) = make_uint4(l[0], l[1], l[2], l[3]);
        }
        __syncthreads();

        if (t + 1 < t1) {
            const int vb = (t + 1) << 4;
            e0 = *(const float4*)(Ebase + vb);
            e1 = *(const float4*)(Ebase + vb + 4);
            const float* Fp = F + (size_t)(vb + fv) * C_ + fc;
            f0 = *(const float4*)(Fp);
            f1 = *(const float4*)(Fp + 4);
        }

        unsigned ahf[2][4], alf[2][4];
        ldx4(ahf[0], aoffH0);
        ldx4(ahf[1], aoffH0 + 16 * 48);
        ldx4(alf[0], aoffL0);
        ldx4(alf[1], aoffL0 + 16 * 48);
#pragma unroll
        for (int nt = 0; nt < 8; ++nt) {
            const unsigned boff = brow * 272 + (wn + nt * 8) * 2;
            unsigned bh[2], bl[2];
            ldx2t(bh, aBh + boff);
            ldx2t(bl, aBl + boff);
#pragma unroll
            for (int mt = 0; mt < 2; ++mt) {
                mma16816(acc[mt][nt], ahf[mt], bh);
                mma16816(acc[mt][nt], ahf[mt], bl);
                mma16816(acc[mt][nt], alf[mt], bh);
            }
        }
    }

#pragma unroll
    for (int mt = 0; mt < 2; ++mt)
#pragma unroll
        for (int nt = 0; nt < 8; ++nt) {
            const int row = wm + mt * 16 + (lane >> 2);
            const int col = wn + nt * 8 + (lane & 3) * 2;
            *(float2*)(out + (size_t)row * C_ + col) =
                make_float2(acc[mt][nt][0], acc[mt][nt][1]);
            *(float2*)(out + (size_t)(row + 8) * C_ + col) =
                make_float2(acc[mt][nt][2], acc[mt][nt][3]);
        }
}

__global__ void reduceA()
{
    const int i = blockIdx.x * 256 + threadIdx.x;
    float s = 0.0f;
#pragma unroll
    for (int c = 0; c < NCHUNK; ++c) s += g_part1[(size_t)c * 8 * K_ * C_ + i];
    g_A[i] = s;
}

__global__ __launch_bounds__(256, 2)
void gemm2()
{
    const int cc = blockIdx.x;
    const int t = blockIdx.y & 1, b = blockIdx.y >> 1;
    const float* P = g_A + ((size_t)(t * B_ + b) * K_) * C_ + cc * 128;
    const float* Q = g_A + ((size_t)b * K_) * C_ + cc * 128;
    float* out = g_AA2 + ((size_t)((cc * 2 + t) * B_ + b) * K_) * K_;

    __shared__ float Ps[16][132];
    __shared__ float Qs[16][132];
    const int tid = threadIdx.x;
    const int lk = tid >> 1, lq = tid & 1;
    const int tm = tid >> 4, tn = tid & 15;

    float acc[8][8];
#pragma unroll
    for (int i = 0; i < 8; ++i)
#pragma unroll
        for (int j = 0; j < 8; ++j) acc[i][j] = 0.0f;

    for (int kt = 0; kt < 8; ++kt) {
        const int c = kt << 4;
        float4 p0 = *(const float4*)(P + (size_t)lk * C_ + c + (lq << 2));
        float4 p1 = *(const float4*)(P + (size_t)lk * C_ + c + (lq << 2) + 8);
        float4 q0 = *(const float4*)(Q + (size_t)lk * C_ + c + (lq << 2));
        float4 q1 = *(const float4*)(Q + (size_t)lk * C_ + c + (lq << 2) + 8);
        __syncthreads();
        const int r0 = lq << 2;
        Ps[r0 + 0][lk] = p0.x; Ps[r0 + 1][lk] = p0.y; Ps[r0 + 2][lk] = p0.z; Ps[r0 + 3][lk] = p0.w;
        Ps[r0 + 8][lk] = p1.x; Ps[r0 + 9][lk] = p1.y; Ps[r0 + 10][lk] = p1.z; Ps[r0 + 11][lk] = p1.w;
        Qs[r0 + 0][lk] = q0.x; Qs[r0 + 1][lk] = q0.y; Qs[r0 + 2][lk] = q0.z; Qs[r0 + 3][lk] = q0.w;
        Qs[r0 + 8][lk] = q1.x; Qs[r0 + 9][lk] = q1.y; Qs[r0 + 10][lk] = q1.z; Qs[r0 + 11][lk] = q1.w;
        __syncthreads();
#pragma unroll
        for (int vv = 0; vv < 16; ++vv) {
            float4 a0 = *(const float4*)&Ps[vv][tm << 2];
            float4 a1 = *(const float4*)&Ps[vv][64 + (tm << 2)];
            float4 b0 = *(const float4*)&Qs[vv][tn << 2];
            float4 b1 = *(const float4*)&Qs[vv][64 + (tn << 2)];
            float a[8] = {a0.x, a0.y, a0.z, a0.w, a1.x, a1.y, a1.z, a1.w};
            float bb[8] = {b0.x, b0.y, b0.z, b0.w, b1.x, b1.y, b1.z, b1.w};
#pragma unroll
            for (int i = 0; i < 8; ++i)
#pragma unroll
                for (int j = 0; j < 8; ++j) acc[i][j] += a[i] * bb[j];
        }
    }
#pragma unroll
    for (int i = 0; i < 8; ++i) {
        const int row = (i < 4) ? ((tm << 2) + i) : (64 + (tm << 2) + i - 4);
        float4 o0 = {acc[i][0], acc[i][1], acc[i][2], acc[i][3]};
        float4 o1 = {acc[i][4], acc[i][5], acc[i][6], acc[i][7]};
        *(float4*)(out + (size_t)row * K_ + (tn << 2)) = o0;
        *(float4*)(out + (size_t)row * K_ + 64 + (tn << 2)) = o1;
    }
}

// ---------------------------------------------------------------------------
// CG solve of (G + D_i) x = rhs_i, one warp per output column i.
// G staged in smem (stride 129, conflict-free); 48 fixed iterations
// (kappa ~ 34 -> rate 0.707/iter -> residual ~1e-7). No factorization.
// ---------------------------------------------------------------------------
__global__ __launch_bounds__(128)
void cgsolve(const float* __restrict__ evx, const float* __restrict__ evy,
             float* __restrict__ outp)
{
    extern __shared__ float Gs[];          // [128][129]

    const int b = blockIdx.x >> 5, grp = blockIdx.x & 31;
    const int tid = threadIdx.x, w = tid >> 5, k = tid & 31;
    const int i = grp * 4 + w;

    const float* X0 = g_AA2 + ((size_t)(0 * B_ + b) * K_) * K_;
    const float* X1 = g_AA2 + ((size_t)(2 * B_ + b) * K_) * K_;
    for (int idx = tid; idx < K_ * K_; idx += 128) {
        const int m = idx >> 7, c = idx & 127;
        Gs[m * LDI + c] = X0[idx] + X1[idx];
    }

    float d[4], x[4], r[4], p[4];
    const float s = fmaxf(evx[b * K_ + K_ - 1], evy[b * K_ + K_ - 1]);
    const float g2 = sqrtf(evy[b * K_ + i] / s);
    const float h2 = 1.0f / (g2 * g2 + 1.0f);
    const float ya = g2 * h2, yb = h2;
    const float* Y0 = g_AA2 + ((size_t)(1 * B_ + b) * K_ + i) * K_;
    const float* Y1 = g_AA2 + ((size_t)(3 * B_ + b) * K_ + i) * K_;
#pragma unroll
    for (int m = 0; m < 4; ++m) {
        const int t = k + 32 * m;
        r[m] = Y0[t] + Y1[t];
        const float g1 = sqrtf(evx[b * K_ + t] / s);
        const float h1 = 1.0f / (g1 * g1 + 1.0f);
        const float re = ya - g1 * h1, im = yb - h1;
        d[m] = LAMBDA * (re * re + im * im);
        x[m] = 0.0f;
        p[m] = r[m];
    }
    __syncthreads();

    float rs = 0.0f;
#pragma unroll
    for (int m = 0; m < 4; ++m) rs += r[m] * r[m];
#pragma unroll
    for (int o = 16; o; o >>= 1) rs += __shfl_xor_sync(0xFFFFFFFFu, rs, o);

    for (int it = 0; it < CG_ITERS; ++it) {
        float Ap0[4] = {0.f, 0.f, 0.f, 0.f}, Ap1[4] = {0.f, 0.f, 0.f, 0.f};
#pragma unroll
        for (int q = 0; q < 4; ++q)
#pragma unroll 8
            for (int j2 = 0; j2 < 32; j2 += 2) {
                const float pj0 = __shfl_sync(0xFFFFFFFFu, p[q], j2);
                const float pj1 = __shfl_sync(0xFFFFFFFFu, p[q], j2 + 1);
                const int j = q * 32 + j2;
#pragma unroll
                for (int m = 0; m < 4; ++m) {
                    Ap0[m] += Gs[j * LDI + k + 32 * m] * pj0;
                    Ap1[m] += Gs[(j + 1) * LDI + k + 32 * m] * pj1;
                }
            }
        float Ap[4];
#pragma unroll
        for (int m = 0; m < 4; ++m) Ap[m] = Ap0[m] + Ap1[m] + d[m] * p[m];

        float pap = 0.0f;
#pragma unroll
        for (int m = 0; m < 4; ++m) pap += p[m] * Ap[m];
#pragma unroll
        for (int o = 16; o; o >>= 1) pap += __shfl_xor_sync(0xFFFFFFFFu, pap, o);
        const float alpha = rs / pap;

        float rs2 = 0.0f;
#pragma unroll
        for (int m = 0; m < 4; ++m) {
            x[m] += alpha * p[m];
            r[m] -= alpha * Ap[m];
            rs2 += r[m] * r[m];
        }
#pragma unroll
        for (int o = 16; o; o >>= 1) rs2 += __shfl_xor_sync(0xFFFFFFFFu, rs2, o);
        const float beta = rs2 / rs;
        rs = rs2;
#pragma unroll
        for (int m = 0; m < 4; ++m) p[m] = r[m] + beta * p[m];
    }

    float* o = outp + ((size_t)(b * K_ + i)) * K_;
#pragma unroll
    for (int m = 0; m < 4; ++m) o[k + 32 * m] = x[m];
}

extern "C" void kernel_launch(void* const* d_in, const int* in_sizes, int n_in,
                              void* d_out, int out_size)
{
    const float* fx  = (const float*)d_in[0];
    const float* fy  = (const float*)d_in[1];
    const float* evx = (const float*)d_in[2];
    const float* evy = (const float*)d_in[3];
    const float* ex  = (const float*)d_in[4];
    const float* ey  = (const float*)d_in[5];
    float* out = (float*)d_out;

    static int attr_done = 0;
    if (!attr_done) {
        cudaFuncSetAttribute(cgsolve, cudaFuncAttributeMaxDynamicSharedMemorySize,
                             K_ * LDI * (int)sizeof(float));
        attr_done = 1;
    }

    gemm1_mma<<<dim3(NCHUNK, 2, 8), 256>>>(fx, fy, ex, ey);
    reduceA<<<(8 * K_ * C_) / 256, 256>>>();
    gemm2<<<dim3(2, 8), 256>>>();
    cgsolve<<<B_ * 32, 128, K_ * LDI * sizeof(float)>>>(evx, evy, out);
}

// round 14
// speedup vs baseline: 1.0915x; 1.0915x over previous
#include <cuda_runtime.h>
#include <cuda_bf16.h>
#include <math.h>

#define B_ 4
#define V_ 50000
#define C_ 256
#define K_ 128
#define LAMBDA 100.0f
#define NCHUNK 19
#define TPC 165
#define NTILES 3125
#define LDI 129

__device__ float g_part1[(size_t)NCHUNK * 8 * K_ * C_];
__device__ float g_A[8 * K_ * C_];
__device__ float g_AA2[2 * 2 * B_ * K_ * K_];
__device__ float g_Lc[B_ * K_ * K_];
__device__ float g_invd[B_ * K_];

__device__ __forceinline__ unsigned smem_u32(const void* p) {
    unsigned a;
    asm("{ .reg .u64 t; cvta.to.shared.u64 t, %1; cvt.u32.u64 %0, t; }" : "=r"(a) : "l"(p));
    return a;
}
__device__ __forceinline__ void cvt2(float x, float y, unsigned& hi, unsigned& lo) {
    __nv_bfloat162 h = __floats2bfloat162_rn(x, y);
    __nv_bfloat162 l = __floats2bfloat162_rn(x - __bfloat162float(h.x),
                                             y - __bfloat162float(h.y));
    hi = *(unsigned*)&h;
    lo = *(unsigned*)&l;
}
__device__ __forceinline__ void ldx4(unsigned* r, unsigned a) {
    asm volatile("ldmatrix.sync.aligned.m8n8.x4.shared.b16 {%0,%1,%2,%3}, [%4];"
                 : "=r"(r[0]), "=r"(r[1]), "=r"(r[2]), "=r"(r[3]) : "r"(a));
}
__device__ __forceinline__ void ldx2t(unsigned* r, unsigned a) {
    asm volatile("ldmatrix.sync.aligned.m8n8.x2.trans.shared.b16 {%0,%1}, [%2];"
                 : "=r"(r[0]), "=r"(r[1]) : "r"(a));
}
__device__ __forceinline__ void mma16816(float* d, const unsigned* a, const unsigned* b) {
    asm volatile("mma.sync.aligned.m16n8k16.row.col.f32.bf16.bf16.f32 "
                 "{%0,%1,%2,%3}, {%4,%5,%6,%7}, {%8,%9}, {%0,%1,%2,%3};"
                 : "+f"(d[0]), "+f"(d[1]), "+f"(d[2]), "+f"(d[3])
                 : "r"(a[0]), "r"(a[1]), "r"(a[2]), "r"(a[3]), "r"(b[0]), "r"(b[1]));
}

// ---------------------------------------------------------------------------
// GEMM1 via mma.sync bf16 hi/lo split (3 passes, single fp32 accumulator),
// software-pipelined: tile t+1's LDG issues before tile t's MMA.
// ---------------------------------------------------------------------------
__global__ __launch_bounds__(256, 2)
void gemm1_mma(const float* __restrict__ fx, const float* __restrict__ fy,
               const float* __restrict__ ex, const float* __restrict__ ey)
{
    __shared__ __align__(16) __nv_bfloat16 Ah[128 * 24], Al[128 * 24];   // stride 48B
    __shared__ __align__(16) __nv_bfloat16 Bh[16 * 136], Bl[16 * 136];   // stride 272B

    const int chunk = blockIdx.x, ntile = blockIdx.y, p = blockIdx.z;
    const int b = p >> 1, which = p & 1;
    const float* E = (which ? ey : ex) + (size_t)b * K_ * V_;
    const float* F = (which ? fy : fx) + (size_t)b * V_ * C_ + ntile * 128;
    float* out = g_part1 + ((size_t)chunk * 8 + which * 4 + b) * K_ * C_ + ntile * 128;

    const int tid = threadIdx.x, wid = tid >> 5, lane = tid & 31;
    const int wm = (wid >> 1) * 32, wn = (wid & 1) * 64;

    const int ar = tid >> 1, ahalf = tid & 1;
    const int fv = tid >> 4, fc = (tid & 15) * 8;

    const unsigned aAh = smem_u32(Ah), aAl = smem_u32(Al);
    const unsigned aBh = smem_u32(Bh), aBl = smem_u32(Bl);

    float acc[2][8][4];
#pragma unroll
    for (int mt = 0; mt < 2; ++mt)
#pragma unroll
        for (int nt = 0; nt < 8; ++nt)
#pragma unroll
            for (int e = 0; e < 4; ++e) acc[mt][nt][e] = 0.0f;

    const unsigned aoffH0 = aAh + (wm + (lane & 15)) * 48 + (lane >> 4) * 16;
    const unsigned aoffL0 = aAl + (wm + (lane & 15)) * 48 + (lane >> 4) * 16;
    const unsigned brow = (lane & 15);

    const int t0 = chunk * TPC;
    const int t1 = (t0 + TPC < NTILES) ? (t0 + TPC) : NTILES;

    const float* Ebase = E + (size_t)ar * V_ + ahalf * 8;

    float4 e0, e1, f0, f1;
    {
        const int vb = t0 << 4;
        e0 = *(const float4*)(Ebase + vb);
        e1 = *(const float4*)(Ebase + vb + 4);
        const float* Fp = F + (size_t)(vb + fv) * C_ + fc;
        f0 = *(const float4*)(Fp);
        f1 = *(const float4*)(Fp + 4);
    }

    for (int t = t0; t < t1; ++t) {
        __syncthreads();
        {
            unsigned h[4], l[4];
            cvt2(e0.x, e0.y, h[0], l[0]); cvt2(e0.z, e0.w, h[1], l[1]);
            cvt2(e1.x, e1.y, h[2], l[2]); cvt2(e1.z, e1.w, h[3], l[3]);
            *(uint4*)((char*)Ah + ar * 48 + ahalf * 16) = make_uint4(h[0], h[1], h[2], h[3]);
            *(uint4*)((char*)Al + ar * 48 + ahalf * 16) = make_uint4(l[0], l[1], l[2], l[3]);
            cvt2(f0.x, f0.y, h[0], l[0]); cvt2(f0.z, f0.w, h[1], l[1]);
            cvt2(f1.x, f1.y, h[2], l[2]); cvt2(f1.z, f1.w, h[3], l[3]);
            *(uint4*)((char*)Bh + fv * 272 + fc * 2) = make_uint4(h[0], h[1], h[2], h[3]);
            *(uint4*)((char*)Bl + fv * 272 + fc * 2) = make_uint4(l[0], l[1], l[2], l[3]);
        }
        __syncthreads();

        if (t + 1 < t1) {
            const int vb = (t + 1) << 4;
            e0 = *(const float4*)(Ebase + vb);
            e1 = *(const float4*)(Ebase + vb + 4);
            const float* Fp = F + (size_t)(vb + fv) * C_ + fc;
            f0 = *(const float4*)(Fp);
            f1 = *(const float4*)(Fp + 4);
        }

        unsigned ahf[2][4], alf[2][4];
        ldx4(ahf[0], aoffH0);
        ldx4(ahf[1], aoffH0 + 16 * 48);
        ldx4(alf[0], aoffL0);
        ldx4(alf[1], aoffL0 + 16 * 48);
#pragma unroll
        for (int nt = 0; nt < 8; ++nt) {
            const unsigned boff = brow * 272 + (wn + nt * 8) * 2;
            unsigned bh[2], bl[2];
            ldx2t(bh, aBh + boff);
            ldx2t(bl, aBl + boff);
#pragma unroll
            for (int mt = 0; mt < 2; ++mt) {
                mma16816(acc[mt][nt], ahf[mt], bh);
                mma16816(acc[mt][nt], ahf[mt], bl);
                mma16816(acc[mt][nt], alf[mt], bh);
            }
        }
    }

#pragma unroll
    for (int mt = 0; mt < 2; ++mt)
#pragma unroll
        for (int nt = 0; nt < 8; ++nt) {
            const int row = wm + mt * 16 + (lane >> 2);
            const int col = wn + nt * 8 + (lane & 3) * 2;
            *(float2*)(out + (size_t)row * C_ + col) =
                make_float2(acc[mt][nt][0], acc[mt][nt][1]);
            *(float2*)(out + (size_t)(row + 8) * C_ + col) =
                make_float2(acc[mt][nt][2], acc[mt][nt][3]);
        }
}

__global__ void reduceA()
{
    const int i = blockIdx.x * 256 + threadIdx.x;
    float s = 0.0f;
#pragma unroll
    for (int c = 0; c < NCHUNK; ++c) s += g_part1[(size_t)c * 8 * K_ * C_ + i];
    g_A[i] = s;
}

__global__ __launch_bounds__(256, 2)
void gemm2()
{
    const int cc = blockIdx.x;
    const int t = blockIdx.y & 1, b = blockIdx.y >> 1;
    const float* P = g_A + ((size_t)(t * B_ + b) * K_) * C_ + cc * 128;
    const float* Q = g_A + ((size_t)b * K_) * C_ + cc * 128;
    float* out = g_AA2 + ((size_t)((cc * 2 + t) * B_ + b) * K_) * K_;

    __shared__ float Ps[16][132];
    __shared__ float Qs[16][132];
    const int tid = threadIdx.x;
    const int lk = tid >> 1, lq = tid & 1;
    const int tm = tid >> 4, tn = tid & 15;

    float acc[8][8];
#pragma unroll
    for (int i = 0; i < 8; ++i)
#pragma unroll
        for (int j = 0; j < 8; ++j) acc[i][j] = 0.0f;

    for (int kt = 0; kt < 8; ++kt) {
        const int c = kt << 4;
        float4 p0 = *(const float4*)(P + (size_t)lk * C_ + c + (lq << 2));
        float4 p1 = *(const float4*)(P + (size_t)lk * C_ + c + (lq << 2) + 8);
        float4 q0 = *(const float4*)(Q + (size_t)lk * C_ + c + (lq << 2));
        float4 q1 = *(const float4*)(Q + (size_t)lk * C_ + c + (lq << 2) + 8);
        __syncthreads();
        const int r0 = lq << 2;
        Ps[r0 + 0][lk] = p0.x; Ps[r0 + 1][lk] = p0.y; Ps[r0 + 2][lk] = p0.z; Ps[r0 + 3][lk] = p0.w;
        Ps[r0 + 8][lk] = p1.x; Ps[r0 + 9][lk] = p1.y; Ps[r0 + 10][lk] = p1.z; Ps[r0 + 11][lk] = p1.w;
        Qs[r0 + 0][lk] = q0.x; Qs[r0 + 1][lk] = q0.y; Qs[r0 + 2][lk] = q0.z; Qs[r0 + 3][lk] = q0.w;
        Qs[r0 + 8][lk] = q1.x; Qs[r0 + 9][lk] = q1.y; Qs[r0 + 10][lk] = q1.z; Qs[r0 + 11][lk] = q1.w;
        __syncthreads();
#pragma unroll
        for (int vv = 0; vv < 16; ++vv) {
            float4 a0 = *(const float4*)&Ps[vv][tm << 2];
            float4 a1 = *(const float4*)&Ps[vv][64 + (tm << 2)];
            float4 b0 = *(const float4*)&Qs[vv][tn << 2];
            float4 b1 = *(const float4*)&Qs[vv][64 + (tn << 2)];
            float a[8] = {a0.x, a0.y, a0.z, a0.w, a1.x, a1.y, a1.z, a1.w};
            float bb[8] = {b0.x, b0.y, b0.z, b0.w, b1.x, b1.y, b1.z, b1.w};
#pragma unroll
            for (int i = 0; i < 8; ++i)
#pragma unroll
                for (int j = 0; j < 8; ++j) acc[i][j] += a[i] * bb[j];
        }
    }
#pragma unroll
    for (int i = 0; i < 8; ++i) {
        const int row = (i < 4) ? ((tm << 2) + i) : (64 + (tm << 2) + i - 4);
        float4 o0 = {acc[i][0], acc[i][1], acc[i][2], acc[i][3]};
        float4 o1 = {acc[i][4], acc[i][5], acc[i][6], acc[i][7]};
        *(float4*)(out + (size_t)row * K_ + (tn << 2)) = o0;
        *(float4*)(out + (size_t)row * K_ + 64 + (tn << 2)) = o1;
    }
}

// ---------------------------------------------------------------------------
// Blocked LDL^T; diag 32x32 block register-resident in warp 0 via MIRROR load
// from the lower triangle (upper triangle in smem is stale for kb>=1 — the
// trailing update only maintains the lower triangle). Symmetry then holds in
// registers and updates use shfl broadcast of row j.
// ---------------------------------------------------------------------------
__global__ __launch_bounds__(256, 1)
void factor()
{
    __shared__ float M[K_ * LDI];
    __shared__ float Wd[96 * 33];
    __shared__ float sinvd[K_];
    const int b = blockIdx.x, tid = threadIdx.x;

    const float* X0 = g_AA2 + ((size_t)(0 * B_ + b) * K_) * K_;
    const float* X1 = g_AA2 + ((size_t)(2 * B_ + b) * K_) * K_;
    for (int idx = tid; idx < K_ * K_; idx += 256) {
        const int m = idx >> 7, c = idx & 127;
        M[m * LDI + c] = X0[idx] + X1[idx];
    }
    __syncthreads();

#pragma unroll
    for (int kb = 0; kb < 4; ++kb) {
        const int j0 = kb << 5;

        // (1) diag block in registers; mirror-load so only the valid lower
        // triangle of smem is read. Rank-1 updates via shfl broadcast.
        if (tid < 32) {
            float row[32];
#pragma unroll
            for (int l = 0; l < 32; ++l)
                row[l] = (l <= tid) ? M[(j0 + tid) * LDI + j0 + l]
                                    : M[(j0 + l) * LDI + j0 + tid];
            float myinv = 0.0f;
#pragma unroll
            for (int j = 0; j < 32; ++j) {
                const float dj = __shfl_sync(0xFFFFFFFFu, row[j], j);
                const float inv = __frcp_rn(dj);
                if (tid == j) myinv = inv;
                const float cf = row[j] * inv;   // = L[tid][j] for tid > j
#pragma unroll
                for (int l = j + 1; l < 32; ++l) {
                    const float v = __shfl_sync(0xFFFFFFFFu, row[l], j);  // A'[j][l]
                    if (tid > j) row[l] -= cf * v;
                }
            }
#pragma unroll
            for (int l = 0; l < 32; ++l)
                if (l <= tid) M[(j0 + tid) * LDI + j0 + l] = row[l];
            sinvd[j0 + tid] = myinv;
        }
        __syncthreads();

        const int nrows = 96 - (kb << 5);
        if (nrows > 0) {
            // (2) panel solve: one thread per row, register recurrence
            if (tid < nrows) {
                const int i = j0 + 32 + tid;
                float w[32];
#pragma unroll
                for (int l = 0; l < 32; ++l) w[l] = M[i * LDI + j0 + l];
#pragma unroll
                for (int l = 0; l < 32; ++l) {
                    const float c = w[l] * sinvd[j0 + l];
#pragma unroll
                    for (int j = l + 1; j < 32; ++j)
                        w[j] -= c * M[(j0 + j) * LDI + j0 + l];
                }
#pragma unroll
                for (int l = 0; l < 32; ++l) {
                    M[i * LDI + j0 + l] = w[l] * sinvd[j0 + l];
                    Wd[tid * 33 + l] = w[l];
                }
            }
            __syncthreads();

            // (3) trailing update, 2x2 register-blocked (lower triangle)
            const int nb = nrows >> 1;
            for (int e = tid; e < nb * nb; e += 256) {
                const int rb = e / nb, cb = e % nb;
                if (cb <= rb) {
                    const int i0 = j0 + 32 + rb * 2, c0 = j0 + 32 + cb * 2;
                    float s00 = 0.f, s01 = 0.f, s10 = 0.f, s11 = 0.f;
#pragma unroll
                    for (int l = 0; l < 32; ++l) {
                        const float m0 = M[i0 * LDI + j0 + l];
                        const float m1 = M[(i0 + 1) * LDI + j0 + l];
                        const float w0 = Wd[(cb * 2) * 33 + l];
                        const float w1 = Wd[(cb * 2 + 1) * 33 + l];
                        s00 += m0 * w0; s01 += m0 * w1;
                        s10 += m1 * w0; s11 += m1 * w1;
                    }
                    M[i0 * LDI + c0]           -= s00;
                    M[i0 * LDI + c0 + 1]       -= s01;
                    M[(i0 + 1) * LDI + c0]     -= s10;
                    M[(i0 + 1) * LDI + c0 + 1] -= s11;
                }
            }
            __syncthreads();
        }
    }

    float* Lc = g_Lc + (size_t)b * K_ * K_;
    for (int idx = tid; idx < K_ * K_; idx += 256) {
        const int j = idx >> 7, r = idx & 127;
        float v;
        if (r < j)       v = 0.0f;
        else if (r == j) v = 1.0f;
        else if ((r >> 5) == (j >> 5)) v = M[r * LDI + j] * sinvd[j];
        else             v = M[r * LDI + j];
        Lc[idx] = v;
    }
    if (tid < K_) g_invd[b * K_ + tid] = sinvd[tid];
}

__global__ __launch_bounds__(128)
void bigsolve(const float* __restrict__ evx, const float* __restrict__ evy,
              float* __restrict__ outp)
{
    extern __shared__ float Ls[];
    __shared__ float sinvd[K_];

    const int b = blockIdx.x >> 5, grp = blockIdx.x & 31;
    const int tid = threadIdx.x, w = tid >> 5, k = tid & 31;
    const int i = grp * 4 + w;

    const float* Lc = g_Lc + (size_t)b * K_ * K_;
    for (int idx = tid; idx < K_ * K_; idx += 128) {
        const int j = idx >> 7, t = idx & 127;
        Ls[j * LDI + t] = Lc[idx];
    }
    if (tid < K_) sinvd[tid] = g_invd[b * K_ + tid];

    float r[4], d[4], x[4], invd_r[4];
    const float s = fmaxf(evx[b * K_ + K_ - 1], evy[b * K_ + K_ - 1]);
    const float g2 = sqrtf(evy[b * K_ + i] / s);
    const float h2 = 1.0f / (g2 * g2 + 1.0f);
    const float ya = g2 * h2, yb = h2;
    const float* Y0 = g_AA2 + ((size_t)(1 * B_ + b) * K_ + i) * K_;
    const float* Y1 = g_AA2 + ((size_t)(3 * B_ + b) * K_ + i) * K_;
#pragma unroll
    for (int m = 0; m < 4; ++m) {
        const int t = k + 32 * m;
        r[m] = Y0[t] + Y1[t];
        const float g1 = sqrtf(evx[b * K_ + t] / s);
        const float h1 = 1.0f / (g1 * g1 + 1.0f);
        const float re = ya - g1 * h1, im = yb - h1;
        d[m] = LAMBDA * (re * re + im * im);
        x[m] = 0.0f;
    }
    __syncthreads();
#pragma unroll
    for (int m = 0; m < 4; ++m) invd_r[m] = sinvd[k + 32 * m];

    for (int it = 0; it < 3; ++it) {
        float y[4];
#pragma unroll
        for (int m = 0; m < 4; ++m) y[m] = r[m] - d[m] * x[m];
#pragma unroll
        for (int q = 0; q < 4; ++q)
            for (int j2 = 0; j2 < 32; ++j2) {
                const int j = q * 32 + j2;
                const float yj = __shfl_sync(0xFFFFFFFFu, y[q], j2);
#pragma unroll
                for (int m = 0; m < 4; ++m)
                    if (m > q || (m == q && k > j2))
                        y[m] -= Ls[j * LDI + k + 32 * m] * yj;
            }
#pragma unroll
        for (int m = 0; m < 4; ++m) y[m] *= invd_r[m];
#pragma unroll
        for (int q = 3; q >= 0; --q)
            for (int j2 = 31; j2 >= 0; --j2) {
                const int j = q * 32 + j2;
                const float yj = __shfl_sync(0xFFFFFFFFu, y[q], j2);
#pragma unroll
                for (int m = 0; m < 4; ++m)
                    if (m < q || (m == q && k < j2))
                        y[m] -= Ls[(k + 32 * m) * LDI + j] * yj;
            }
#pragma unroll
        for (int m = 0; m < 4; ++m) x[m] = y[m];
    }
    float* o = outp + ((size_t)(b * K_ + i)) * K_;
#pragma unroll
    for (int m = 0; m < 4; ++m) o[k + 32 * m] = x[m];
}

extern "C" void kernel_launch(void* const* d_in, const int* in_sizes, int n_in,
                              void* d_out, int out_size)
{
    const float* fx  = (const float*)d_in[0];
    const float* fy  = (const float*)d_in[1];
    const float* evx = (const float*)d_in[2];
    const float* evy = (const float*)d_in[3];
    const float* ex  = (const float*)d_in[4];
    const float* ey  = (const float*)d_in[5];
    float* out = (float*)d_out;

    static int attr_done = 0;
    if (!attr_done) {
        cudaFuncSetAttribute(bigsolve, cudaFuncAttributeMaxDynamicSharedMemorySize,
                             K_ * LDI * (int)sizeof(float));
        attr_done = 1;
    }

    gemm1_mma<<<dim3(NCHUNK, 2, 8), 256>>>(fx, fy, ex, ey);
    reduceA<<<(8 * K_ * C_) / 256, 256>>>();
    gemm2<<<dim3(2, 8), 256>>>();
    factor<<<B_, 256>>>();
    bigsolve<<<B_ * 32, 128, K_ * LDI * sizeof(float)>>>(evx, evy, out);
}